// round 1
// baseline (speedup 1.0000x reference)
#include <cuda_runtime.h>
#include <math.h>

// Problem dims
#define B_   64
#define T_   256
#define U_   1024
#define G3   3072           // 3*U
#define M_   (B_ * T_)      // 16384 rows for the big input-projection GEMMs

// Recurrent persistent-kernel config
#define GRID_R   128        // co-resident CTAs (<=148 SMs)
#define THR_R    256
#define KSPLIT   16         // K=1024 split 16 ways (64 each)
#define NSPLIT   8          // N=3072 split 8 ways (384 each)
#define NCOLS    384
#define KTILE    64
#define KCHUNK   16

// -------- device scratch (no allocation allowed; use __device__ globals) ----
__device__ float g_xp[(size_t)M_ * G3];      // 192 MB : input projections
__device__ float g_y1[(size_t)M_ * U_];      //  64 MB : layer-1 outputs
__device__ float g_Ut[(size_t)G3 * U_];      //  12 MB : transposed recurrent kernel
__device__ float g_rp[(size_t)KSPLIT * B_ * G3]; // 12.6 MB : split-K partials
__device__ float g_h[B_ * U_];               // 256 KB : hidden state
__device__ unsigned g_bar_count;
__device__ unsigned g_bar_gen;

// -------- software grid barrier (all GRID_R CTAs co-resident) ---------------
__device__ __forceinline__ void grid_sync() {
    __syncthreads();
    if (threadIdx.x == 0) {
        __threadfence();
        unsigned gen = *(volatile unsigned*)&g_bar_gen;
        if (atomicAdd(&g_bar_count, 1u) == GRID_R - 1) {
            g_bar_count = 0;
            __threadfence();
            atomicAdd(&g_bar_gen, 1u);
        } else {
            while (*(volatile unsigned*)&g_bar_gen == gen) { }
        }
        __threadfence();
    }
    __syncthreads();
}

// ---------------------------------------------------------------------------
// Transpose U [1024, 3072] -> Ut [3072, 1024]
// ---------------------------------------------------------------------------
__global__ void transpose_kernel(const float* __restrict__ U) {
    __shared__ float tile[32][33];
    int bx = blockIdx.x;             // over 3072 cols (96 blocks)
    int by = blockIdx.y;             // over 1024 rows (32 blocks)
    int tx = threadIdx.x;
    int x  = bx * 32 + tx;           // col in U
    int y0 = by * 32;
    #pragma unroll
    for (int r = threadIdx.y; r < 32; r += 8)
        tile[r][tx] = U[(size_t)(y0 + r) * G3 + x];
    __syncthreads();
    int xo = by * 32 + tx;           // col in Ut (= row in U)
    int yo0 = bx * 32;               // row in Ut (= col in U)
    #pragma unroll
    for (int r = threadIdx.y; r < 32; r += 8)
        g_Ut[(size_t)(yo0 + r) * U_ + xo] = tile[tx][r];
}

// ---------------------------------------------------------------------------
// SGEMM + bias: C[M_,G3] = A[M_,1024] @ W[1024,G3] + bias[n]
// A is either external (x) or the internal g_y1. C is always g_xp.
// 128x128 tile, BK=8, 256 threads, 8x8 microtile (split 4+4 for float4 LDS).
// ---------------------------------------------------------------------------
__global__ __launch_bounds__(256) void sgemm_bias_kernel(
    const float* __restrict__ A_ext,
    const float* __restrict__ W,
    const float* __restrict__ bias,
    int A_internal)
{
    const float* A = A_internal ? g_y1 : A_ext;
    __shared__ float As[8][128];
    __shared__ float Bs[8][128];
    int tid  = threadIdx.x;
    int row0 = blockIdx.y * 128;
    int col0 = blockIdx.x * 128;
    int tr = tid >> 4;               // 0..15
    int tc = tid & 15;               // 0..15

    int am = tid >> 1;               // 0..127
    int ak = (tid & 1) * 4;          // 0 or 4
    int bk = tid >> 5;               // 0..7
    int bn = (tid & 31) * 4;         // 0..124

    float acc[8][8];
    #pragma unroll
    for (int i = 0; i < 8; i++)
        #pragma unroll
        for (int j = 0; j < 8; j++) acc[i][j] = 0.f;

    for (int k0 = 0; k0 < 1024; k0 += 8) {
        float4 a4 = *(const float4*)&A[(size_t)(row0 + am) * 1024 + k0 + ak];
        As[ak + 0][am] = a4.x;
        As[ak + 1][am] = a4.y;
        As[ak + 2][am] = a4.z;
        As[ak + 3][am] = a4.w;
        float4 b4 = *(const float4*)&W[(size_t)(k0 + bk) * G3 + col0 + bn];
        *(float4*)&Bs[bk][bn] = b4;
        __syncthreads();
        #pragma unroll
        for (int kk = 0; kk < 8; kk++) {
            float4 a0 = *(float4*)&As[kk][tr * 4];
            float4 a1 = *(float4*)&As[kk][64 + tr * 4];
            float4 b0 = *(float4*)&Bs[kk][tc * 4];
            float4 b1 = *(float4*)&Bs[kk][64 + tc * 4];
            float av[8] = {a0.x, a0.y, a0.z, a0.w, a1.x, a1.y, a1.z, a1.w};
            float bv[8] = {b0.x, b0.y, b0.z, b0.w, b1.x, b1.y, b1.z, b1.w};
            #pragma unroll
            for (int i = 0; i < 8; i++)
                #pragma unroll
                for (int j = 0; j < 8; j++)
                    acc[i][j] += av[i] * bv[j];
        }
        __syncthreads();
    }

    #pragma unroll
    for (int i = 0; i < 8; i++) {
        int r = row0 + ((i < 4) ? (tr * 4 + i) : (64 + tr * 4 + i - 4));
        #pragma unroll
        for (int j = 0; j < 8; j++) {
            int c = col0 + ((j < 4) ? (tc * 4 + j) : (64 + tc * 4 + j - 4));
            g_xp[(size_t)r * G3 + c] = acc[i][j] + bias[c];
        }
    }
}

// ---------------------------------------------------------------------------
// Persistent GRU recurrence. GRID_R CTAs x THR_R threads, grid-synced.
// Per step:
//   Phase A: rp = h @ U  (split-K x split-N, partials into g_rp)
//   Phase B: gate math, h update, write y[t]
// ---------------------------------------------------------------------------
__global__ __launch_bounds__(THR_R, 1) void gru_recurrent_kernel(
    const float* __restrict__ bias_r,   // b[1] row (3072)
    const float* __restrict__ h0,       // initial hidden or nullptr (zeros)
    float* __restrict__ y_ext,          // output sequence target (if !y_internal)
    int y_internal,                     // 1 -> write g_y1
    float* __restrict__ state_out)      // final hidden or nullptr
{
    __shared__ float hs[64][KCHUNK + 1];     // h chunk  [b][k]
    __shared__ float us[NCOLS][KCHUNK + 1];  // Ut chunk [j][k]

    const int tid = threadIdx.x;
    const int bid = blockIdx.x;
    const int tb  = tid >> 5;   // 0..7  (warp id -> 8 batch rows)
    const int tj  = tid & 31;   // lane  -> 12 interleaved columns
    const int ks  = bid >> 3;   // 0..15 K slice
    const int ns  = bid & 7;    // 0..7  N slice

    float* y = y_internal ? g_y1 : y_ext;

    // init hidden state
    for (int i = bid * THR_R + tid; i < B_ * U_; i += GRID_R * THR_R)
        g_h[i] = h0 ? h0[i] : 0.f;
    grid_sync();

    for (int t = 0; t < T_; t++) {
        // ---------------- Phase A: partial rp = h @ U ----------------
        float acc[8][12];
        #pragma unroll
        for (int i = 0; i < 8; i++)
            #pragma unroll
            for (int jj = 0; jj < 12; jj++) acc[i][jj] = 0.f;

        #pragma unroll
        for (int c = 0; c < KTILE / KCHUNK; c++) {
            const int kb = ks * KTILE + c * KCHUNK;
            // stage h chunk: 64 x 16 floats (256 float4 loads, 1 per thread)
            {
                int b = tid >> 2, q = tid & 3;
                float4 h4 = __ldcg((const float4*)&g_h[b * U_ + kb + q * 4]);
                hs[b][q * 4 + 0] = h4.x;
                hs[b][q * 4 + 1] = h4.y;
                hs[b][q * 4 + 2] = h4.z;
                hs[b][q * 4 + 3] = h4.w;
            }
            // stage Ut chunk: 384 x 16 floats (1536 float4 loads, 6 per thread)
            #pragma unroll
            for (int w = 0; w < 6; w++) {
                int fidx = tid + w * THR_R;      // 0..1535
                int j = fidx >> 2, q = fidx & 3;
                float4 u4 = *(const float4*)&g_Ut[(size_t)(ns * NCOLS + j) * U_ + kb + q * 4];
                us[j][q * 4 + 0] = u4.x;
                us[j][q * 4 + 1] = u4.y;
                us[j][q * 4 + 2] = u4.z;
                us[j][q * 4 + 3] = u4.w;
            }
            __syncthreads();
            #pragma unroll
            for (int k = 0; k < KCHUNK; k++) {
                float hv[8], uv[12];
                #pragma unroll
                for (int i = 0; i < 8; i++) hv[i] = hs[tb * 8 + i][k];
                #pragma unroll
                for (int jj = 0; jj < 12; jj++) uv[jj] = us[tj + 32 * jj][k];
                #pragma unroll
                for (int i = 0; i < 8; i++)
                    #pragma unroll
                    for (int jj = 0; jj < 12; jj++)
                        acc[i][jj] += hv[i] * uv[jj];
            }
            __syncthreads();
        }
        // store partials (coalesced along tj)
        #pragma unroll
        for (int i = 0; i < 8; i++) {
            int b = tb * 8 + i;
            size_t base = (size_t)ks * B_ * G3 + (size_t)b * G3 + ns * NCOLS + tj;
            #pragma unroll
            for (int jj = 0; jj < 12; jj++)
                g_rp[base + 32 * jj] = acc[i][jj];
        }
        grid_sync();

        // ---------------- Phase B: gates + h update ----------------
        for (int e = bid * THR_R + tid; e < B_ * U_; e += GRID_R * THR_R) {
            int b = e >> 10;
            int j = e & 1023;
            float rz = bias_r[j];
            float rr = bias_r[U_ + j];
            float rh = bias_r[2 * U_ + j];
            size_t rb = (size_t)b * G3 + j;
            #pragma unroll
            for (int p = 0; p < KSPLIT; p++) {
                size_t off = (size_t)p * B_ * G3 + rb;
                rz += __ldcg(&g_rp[off]);
                rr += __ldcg(&g_rp[off + U_]);
                rh += __ldcg(&g_rp[off + 2 * U_]);
            }
            const float* xrow = &g_xp[(size_t)(b * T_ + t) * G3];
            float xz = xrow[j];
            float xr = xrow[U_ + j];
            float xh = xrow[2 * U_ + j];
            float z = 1.f / (1.f + expf(-(xz + rz)));
            float r = 1.f / (1.f + expf(-(xr + rr)));
            float hh = tanhf(xh + r * rh);
            float hold = g_h[e];     // written by this same thread last step
            float hnew = z * hold + (1.f - z) * hh;
            g_h[e] = hnew;
            y[(size_t)(b * T_ + t) * U_ + j] = hnew;
        }
        grid_sync();
    }

    if (state_out) {
        for (int i = bid * THR_R + tid; i < B_ * U_; i += GRID_R * THR_R)
            state_out[i] = __ldcg(&g_h[i]);
    }
}

// ---------------------------------------------------------------------------
extern "C" void kernel_launch(void* const* d_in, const int* in_sizes, int n_in,
                              void* d_out, int out_size) {
    (void)in_sizes; (void)n_in; (void)out_size;
    const float* x      = (const float*)d_in[0];
    const float* hidden = (const float*)d_in[1];
    const float* W1     = (const float*)d_in[2];
    const float* U1     = (const float*)d_in[3];
    const float* b1     = (const float*)d_in[4];
    const float* W2     = (const float*)d_in[5];
    const float* U2     = (const float*)d_in[6];
    const float* b2     = (const float*)d_in[7];
    float* out   = (float*)d_out;
    float* state = out + (size_t)M_ * U_;

    dim3 tB(32, 8), tG(96, 32);
    dim3 gG(G3 / 128, M_ / 128);

    // ---- Layer 1 ----
    transpose_kernel<<<tG, tB>>>(U1);
    sgemm_bias_kernel<<<gG, 256>>>(x, W1, b1, /*A_internal=*/0);
    gru_recurrent_kernel<<<GRID_R, THR_R>>>(b1 + G3, hidden,
                                            nullptr, /*y_internal=*/1, nullptr);
    // ---- Layer 2 ----
    transpose_kernel<<<tG, tB>>>(U2);
    sgemm_bias_kernel<<<gG, 256>>>(nullptr, W2, b2, /*A_internal=*/1);
    gru_recurrent_kernel<<<GRID_R, THR_R>>>(b2 + G3, nullptr,
                                            out, /*y_internal=*/0, state);
}

// round 2
// speedup vs baseline: 2.0104x; 2.0104x over previous
#include <cuda_runtime.h>
#include <cuda_bf16.h>
#include <math.h>

// Problem dims
#define B_   64
#define T_   256
#define U_   1024
#define G3   3072
#define M_   (B_ * T_)

// Recurrent persistent-kernel config
#define GRID_R   128
#define THR_R    256
#define KSPLIT   8          // K=1024 split 8 ways (128 each)
#define NSPLIT   16         // N=3072 split 16 ways (192 each)
#define NCOLS    192
#define KTILE    128
#define UST      136        // smem row stride (halves) for Ut slice (128 + 8 pad)
#define HST      136        // smem row stride for h slice

// Big-GEMM config
#define AST      40         // smem row stride (halves) for 32-k chunks (32 + 8 pad)

// -------- device scratch --------------------------------------------------
__device__ float          g_xp [(size_t)M_ * G3];     // 192 MB input projections (fp32)
__device__ unsigned short g_xhi[(size_t)M_ * U_];
__device__ unsigned short g_xlo[(size_t)M_ * U_];
__device__ unsigned short g_y1hi[(size_t)M_ * U_];
__device__ unsigned short g_y1lo[(size_t)M_ * U_];
__device__ unsigned short g_wthi[(size_t)G3 * U_];
__device__ unsigned short g_wtlo[(size_t)G3 * U_];
__device__ unsigned short g_uthi[(size_t)G3 * U_];
__device__ unsigned short g_utlo[(size_t)G3 * U_];
__device__ float          g_rp [(size_t)KSPLIT * B_ * G3];
__device__ float          g_h  [B_ * U_];
__device__ unsigned short g_hhi[B_ * U_];
__device__ unsigned short g_hlo[B_ * U_];
__device__ unsigned g_bar_count;
__device__ unsigned g_bar_gen;

// -------- helpers ---------------------------------------------------------
__device__ __forceinline__ void split2(float v, unsigned short& hi, unsigned short& lo) {
    __nv_bfloat16 h = __float2bfloat16(v);
    float r = v - __bfloat162float(h);
    __nv_bfloat16 l = __float2bfloat16(r);
    hi = *(unsigned short*)&h;
    lo = *(unsigned short*)&l;
}

__device__ __forceinline__ void ldsm4(unsigned (&r)[4], unsigned addr) {
    asm volatile("ldmatrix.sync.aligned.m8n8.x4.shared.b16 {%0,%1,%2,%3}, [%4];"
                 : "=r"(r[0]), "=r"(r[1]), "=r"(r[2]), "=r"(r[3]) : "r"(addr));
}

__device__ __forceinline__ void mma16816(float (&c)[4],
    unsigned a0, unsigned a1, unsigned a2, unsigned a3, unsigned b0, unsigned b1) {
    asm volatile(
        "mma.sync.aligned.m16n8k16.row.col.f32.bf16.bf16.f32 "
        "{%0,%1,%2,%3}, {%4,%5,%6,%7}, {%8,%9}, {%0,%1,%2,%3};"
        : "+f"(c[0]), "+f"(c[1]), "+f"(c[2]), "+f"(c[3])
        : "r"(a0), "r"(a1), "r"(a2), "r"(a3), "r"(b0), "r"(b1));
}

// Generic warp MMA tile: MSUB m16 subtiles x NSUB n8 subtiles at k16 offset kbase.
template<int MSUB, int NSUB, int ASTR, int BSTR>
__device__ __forceinline__ void mma_tile(
    const unsigned short* As, const unsigned short* Bs,
    int mb, int nb, int kbase,
    int a_ro, int a_ko, int b_ro, int b_ko,
    float acc[][NSUB][4])
{
    unsigned aF[MSUB][4], bF[NSUB / 2][4];
    #pragma unroll
    for (int i = 0; i < MSUB; i++) {
        unsigned ad = (unsigned)__cvta_generic_to_shared(
            &As[(mb + i * 16 + a_ro) * ASTR + kbase + a_ko]);
        ldsm4(aF[i], ad);
    }
    #pragma unroll
    for (int p = 0; p < NSUB / 2; p++) {
        unsigned bd = (unsigned)__cvta_generic_to_shared(
            &Bs[(nb + p * 16 + b_ro) * BSTR + kbase + b_ko]);
        ldsm4(bF[p], bd);
    }
    #pragma unroll
    for (int i = 0; i < MSUB; i++)
        #pragma unroll
        for (int j = 0; j < NSUB; j++) {
            int p = j >> 1, q = (j & 1) << 1;
            mma16816(acc[i][j], aF[i][0], aF[i][1], aF[i][2], aF[i][3],
                     bF[p][q], bF[p][q + 1]);
        }
}

// -------- software grid barrier -------------------------------------------
__device__ __forceinline__ void grid_sync() {
    __syncthreads();
    if (threadIdx.x == 0) {
        __threadfence();
        unsigned gen = *(volatile unsigned*)&g_bar_gen;
        if (atomicAdd(&g_bar_count, 1u) == GRID_R - 1) {
            g_bar_count = 0;
            __threadfence();
            atomicAdd(&g_bar_gen, 1u);
        } else {
            while (*(volatile unsigned*)&g_bar_gen == gen) { }
        }
        __threadfence();
    }
    __syncthreads();
}

// ---------------------------------------------------------------------------
// Split x (fp32) -> bf16 hi/lo
// ---------------------------------------------------------------------------
__global__ void split_x_kernel(const float* __restrict__ x) {
    size_t n4 = (size_t)M_ * U_ / 4;
    for (size_t i = (size_t)blockIdx.x * blockDim.x + threadIdx.x; i < n4;
         i += (size_t)gridDim.x * blockDim.x) {
        float4 v = ((const float4*)x)[i];
        unsigned short h0, h1, h2, h3, l0, l1, l2, l3;
        split2(v.x, h0, l0); split2(v.y, h1, l1);
        split2(v.z, h2, l2); split2(v.w, h3, l3);
        ((ushort4*)g_xhi)[i] = make_ushort4(h0, h1, h2, h3);
        ((ushort4*)g_xlo)[i] = make_ushort4(l0, l1, l2, l3);
    }
}

// ---------------------------------------------------------------------------
// Transpose + split: M[1024,3072] fp32 -> dest[3072,1024] bf16 hi/lo
// dest: 0 -> (g_wthi,g_wtlo), 1 -> (g_uthi,g_utlo)
// ---------------------------------------------------------------------------
__global__ void transpose_split_kernel(const float* __restrict__ Min, int dest) {
    __shared__ float tile[32][33];
    unsigned short* dh = dest ? g_uthi : g_wthi;
    unsigned short* dl = dest ? g_utlo : g_wtlo;
    int bx = blockIdx.x, by = blockIdx.y, tx = threadIdx.x;
    int x = bx * 32 + tx;
    int y0 = by * 32;
    #pragma unroll
    for (int r = threadIdx.y; r < 32; r += 8)
        tile[r][tx] = Min[(size_t)(y0 + r) * G3 + x];
    __syncthreads();
    int xo = by * 32 + tx;
    int yo0 = bx * 32;
    #pragma unroll
    for (int r = threadIdx.y; r < 32; r += 8) {
        unsigned short hi, lo;
        split2(tile[tx][r], hi, lo);
        dh[(size_t)(yo0 + r) * U_ + xo] = hi;
        dl[(size_t)(yo0 + r) * U_ + xo] = lo;
    }
}

// ---------------------------------------------------------------------------
// Big GEMM (tensor core, split-bf16 x3): C[M_,G3] = A[M_,1024]@W[1024,G3] + bias
// A = x splits (a_sel=0) or y1 splits (a_sel=1); B = g_wt splits; C = g_xp fp32.
// CTA 128x128, BK=32, 8 warps as 2m x 4n (warp tile 64x32).
// ---------------------------------------------------------------------------
__global__ __launch_bounds__(256) void gemm_mma_kernel(
    const float* __restrict__ bias, int a_sel)
{
    const unsigned short* Ahg = a_sel ? g_y1hi : g_xhi;
    const unsigned short* Alg = a_sel ? g_y1lo : g_xlo;
    __shared__ __align__(16) unsigned short Ah[128 * AST], Al[128 * AST];
    __shared__ __align__(16) unsigned short Bh[128 * AST], Bl[128 * AST];

    const int tid = threadIdx.x, w = tid >> 5, l = tid & 31;
    const int row0 = blockIdx.y * 128, col0 = blockIdx.x * 128;
    const int mb = (w >> 2) * 64, nb = (w & 3) * 32;

    const int asel = l >> 3;
    const int a_ro = ((asel & 1) << 3) + (l & 7);
    const int a_ko = (asel >> 1) << 3;
    const int b_ro = ((asel >> 1) << 3) + (l & 7);
    const int b_ko = (asel & 1) << 3;

    // staging: 512 16B segs per array, 2 per thread
    const int s0 = tid, s1 = tid + 256;
    const int r0 = s0 >> 2, k0s = (s0 & 3) << 3;
    const int r1 = s1 >> 2, k1s = (s1 & 3) << 3;

    float acc[4][4][4];
    #pragma unroll
    for (int i = 0; i < 4; i++)
        #pragma unroll
        for (int j = 0; j < 4; j++)
            #pragma unroll
            for (int c = 0; c < 4; c++) acc[i][j][c] = 0.f;

    for (int k0 = 0; k0 < U_; k0 += 32) {
        uint4 vah0 = *(const uint4*)&Ahg[(size_t)(row0 + r0) * U_ + k0 + k0s];
        uint4 vah1 = *(const uint4*)&Ahg[(size_t)(row0 + r1) * U_ + k0 + k1s];
        uint4 val0 = *(const uint4*)&Alg[(size_t)(row0 + r0) * U_ + k0 + k0s];
        uint4 val1 = *(const uint4*)&Alg[(size_t)(row0 + r1) * U_ + k0 + k1s];
        uint4 vbh0 = *(const uint4*)&g_wthi[(size_t)(col0 + r0) * U_ + k0 + k0s];
        uint4 vbh1 = *(const uint4*)&g_wthi[(size_t)(col0 + r1) * U_ + k0 + k1s];
        uint4 vbl0 = *(const uint4*)&g_wtlo[(size_t)(col0 + r0) * U_ + k0 + k0s];
        uint4 vbl1 = *(const uint4*)&g_wtlo[(size_t)(col0 + r1) * U_ + k0 + k1s];
        __syncthreads();
        *(uint4*)&Ah[r0 * AST + k0s] = vah0;
        *(uint4*)&Ah[r1 * AST + k1s] = vah1;
        *(uint4*)&Al[r0 * AST + k0s] = val0;
        *(uint4*)&Al[r1 * AST + k1s] = val1;
        *(uint4*)&Bh[r0 * AST + k0s] = vbh0;
        *(uint4*)&Bh[r1 * AST + k1s] = vbh1;
        *(uint4*)&Bl[r0 * AST + k0s] = vbl0;
        *(uint4*)&Bl[r1 * AST + k1s] = vbl1;
        __syncthreads();
        #pragma unroll
        for (int kk = 0; kk < 2; kk++) {
            mma_tile<4, 4, AST, AST>(Ah, Bh, mb, nb, kk * 16, a_ro, a_ko, b_ro, b_ko, acc);
            mma_tile<4, 4, AST, AST>(Ah, Bl, mb, nb, kk * 16, a_ro, a_ko, b_ro, b_ko, acc);
            mma_tile<4, 4, AST, AST>(Al, Bh, mb, nb, kk * 16, a_ro, a_ko, b_ro, b_ko, acc);
        }
    }

    #pragma unroll
    for (int i = 0; i < 4; i++)
        #pragma unroll
        for (int j = 0; j < 4; j++) {
            int r = row0 + mb + i * 16 + (l >> 2);
            int c = col0 + nb + j * 8 + ((l & 3) << 1);
            float bz0 = bias[c], bz1 = bias[c + 1];
            *(float2*)&g_xp[(size_t)r * G3 + c] =
                make_float2(acc[i][j][0] + bz0, acc[i][j][1] + bz1);
            *(float2*)&g_xp[(size_t)(r + 8) * G3 + c] =
                make_float2(acc[i][j][2] + bz0, acc[i][j][3] + bz1);
        }
}

// ---------------------------------------------------------------------------
// Persistent GRU recurrence (tensor core phase A, Ut slice resident in smem)
// 128 CTAs = 8 K-slices x 16 N-slices. Per step:
//   A: rp_partial = h @ U (split-bf16 x3 mma) -> g_rp ; grid_sync
//   B: reduce partials + gates + h update + y write ; grid_sync
// ---------------------------------------------------------------------------
#define SMEM_DYN ((NCOLS * UST * 2 + 64 * HST * 2) * 2)   // bytes = 139264

__global__ __launch_bounds__(THR_R, 1) void gru_recurrent_kernel(
    const float* __restrict__ bias_r,
    const float* __restrict__ h0,
    float* __restrict__ y_ext,
    int y_internal,
    float* __restrict__ state_out)
{
    extern __shared__ __align__(16) unsigned short sm[];
    unsigned short* us_hi = sm;
    unsigned short* us_lo = us_hi + NCOLS * UST;
    unsigned short* hs_hi = us_lo + NCOLS * UST;
    unsigned short* hs_lo = hs_hi + 64 * HST;

    const int tid = threadIdx.x, bid = blockIdx.x;
    const int w = tid >> 5, l = tid & 31;
    const int ks = bid >> 4;      // 0..7
    const int ns = bid & 15;      // 0..15

    // init hidden state (+ splits)
    for (int i = bid * THR_R + tid; i < B_ * U_; i += GRID_R * THR_R) {
        float v = h0 ? h0[i] : 0.f;
        g_h[i] = v;
        unsigned short hi, lo;
        split2(v, hi, lo);
        g_hhi[i] = hi;
        g_hlo[i] = lo;
    }

    // preload Ut slice into smem (hi & lo): NCOLS rows x KTILE halves
    for (int s = tid; s < NCOLS * (KTILE / 8); s += THR_R) {
        int row = s >> 4, k8 = (s & 15) << 3;
        size_t g = (size_t)(ns * NCOLS + row) * U_ + ks * KTILE + k8;
        *(uint4*)&us_hi[row * UST + k8] = *(const uint4*)&g_uthi[g];
        *(uint4*)&us_lo[row * UST + k8] = *(const uint4*)&g_utlo[g];
    }
    grid_sync();

    const int asel = l >> 3;
    const int a_ro = ((asel & 1) << 3) + (l & 7);
    const int a_ko = (asel >> 1) << 3;
    const int b_ro = ((asel >> 1) << 3) + (l & 7);
    const int b_ko = (asel & 1) << 3;
    const int mb = (w >> 2) * 32;   // warp grid 2m x 4n, warp tile 32x48
    const int nb = (w & 3) * 48;

    for (int t = 0; t < T_; t++) {
        // ---- stage h slice: 64 rows x KTILE halves (hi & lo) ----
        #pragma unroll
        for (int q = 0; q < 4; q++) {
            int s = tid + q * THR_R;          // 0..1023
            int row = s >> 4, k8 = (s & 15) << 3;
            size_t g = (size_t)row * U_ + ks * KTILE + k8;
            *(uint4*)&hs_hi[row * HST + k8] = __ldcg((const uint4*)&g_hhi[g]);
            *(uint4*)&hs_lo[row * HST + k8] = __ldcg((const uint4*)&g_hlo[g]);
        }
        __syncthreads();

        // ---- Phase A: mma over K=KTILE, 3 split passes ----
        float acc[2][6][4];
        #pragma unroll
        for (int i = 0; i < 2; i++)
            #pragma unroll
            for (int j = 0; j < 6; j++)
                #pragma unroll
                for (int c = 0; c < 4; c++) acc[i][j][c] = 0.f;

        #pragma unroll
        for (int k16 = 0; k16 < KTILE / 16; k16++) {
            mma_tile<2, 6, HST, UST>(hs_hi, us_hi, mb, nb, k16 * 16, a_ro, a_ko, b_ro, b_ko, acc);
            mma_tile<2, 6, HST, UST>(hs_hi, us_lo, mb, nb, k16 * 16, a_ro, a_ko, b_ro, b_ko, acc);
            mma_tile<2, 6, HST, UST>(hs_lo, us_hi, mb, nb, k16 * 16, a_ro, a_ko, b_ro, b_ko, acc);
        }

        // ---- store partials ----
        {
            size_t base = (size_t)ks * B_ * G3;
            #pragma unroll
            for (int i = 0; i < 2; i++)
                #pragma unroll
                for (int j = 0; j < 6; j++) {
                    int r = mb + i * 16 + (l >> 2);
                    int c = ns * NCOLS + nb + j * 8 + ((l & 3) << 1);
                    *(float2*)&g_rp[base + (size_t)r * G3 + c] =
                        make_float2(acc[i][j][0], acc[i][j][1]);
                    *(float2*)&g_rp[base + (size_t)(r + 8) * G3 + c] =
                        make_float2(acc[i][j][2], acc[i][j][3]);
                }
        }
        grid_sync();

        // ---- Phase B: reduce partials, gates, h update ----
        #pragma unroll
        for (int q = 0; q < 2; q++) {
            int e = bid * THR_R + tid + q * GRID_R * THR_R;  // 0..65535
            int b = e >> 10;
            int j = e & 1023;
            float rz = bias_r[j];
            float rr = bias_r[U_ + j];
            float rh = bias_r[2 * U_ + j];
            size_t rb = (size_t)b * G3 + j;
            #pragma unroll
            for (int p = 0; p < KSPLIT; p++) {
                size_t off = (size_t)p * B_ * G3 + rb;
                rz += __ldcg(&g_rp[off]);
                rr += __ldcg(&g_rp[off + U_]);
                rh += __ldcg(&g_rp[off + 2 * U_]);
            }
            const float* xr = &g_xp[(size_t)(b * T_ + t) * G3];
            float xz = xr[j];
            float xrr = xr[U_ + j];
            float xh = xr[2 * U_ + j];
            float z = 1.f / (1.f + expf(-(xz + rz)));
            float r = 1.f / (1.f + expf(-(xrr + rr)));
            float hh = tanhf(xh + r * rh);
            float hold = g_h[e];
            float hnew = z * hold + (1.f - z) * hh;
            g_h[e] = hnew;
            unsigned short hi, lo;
            split2(hnew, hi, lo);
            g_hhi[e] = hi;
            g_hlo[e] = lo;
            size_t yi = (size_t)(b * T_ + t) * U_ + j;
            if (y_internal) {
                g_y1hi[yi] = hi;
                g_y1lo[yi] = lo;
            } else {
                y_ext[yi] = hnew;
            }
        }
        grid_sync();
    }

    if (state_out)
        for (int i = bid * THR_R + tid; i < B_ * U_; i += GRID_R * THR_R)
            state_out[i] = g_h[i];
}

// ---------------------------------------------------------------------------
extern "C" void kernel_launch(void* const* d_in, const int* in_sizes, int n_in,
                              void* d_out, int out_size) {
    (void)in_sizes; (void)n_in; (void)out_size;
    const float* x      = (const float*)d_in[0];
    const float* hidden = (const float*)d_in[1];
    const float* W1     = (const float*)d_in[2];
    const float* U1     = (const float*)d_in[3];
    const float* b1     = (const float*)d_in[4];
    const float* W2     = (const float*)d_in[5];
    const float* U2     = (const float*)d_in[6];
    const float* b2     = (const float*)d_in[7];
    float* out   = (float*)d_out;
    float* state = out + (size_t)M_ * U_;

    cudaFuncSetAttribute(gru_recurrent_kernel,
                         cudaFuncAttributeMaxDynamicSharedMemorySize, SMEM_DYN);

    dim3 tB(32, 8), tG(96, 32);
    dim3 gG(G3 / 128, M_ / 128);

    // ---- Layer 1 ----
    split_x_kernel<<<2048, 256>>>(x);
    transpose_split_kernel<<<tG, tB>>>(W1, 0);
    transpose_split_kernel<<<tG, tB>>>(U1, 1);
    gemm_mma_kernel<<<gG, 256>>>(b1, 0);
    gru_recurrent_kernel<<<GRID_R, THR_R, SMEM_DYN>>>(b1 + G3, hidden,
                                                      nullptr, 1, nullptr);
    // ---- Layer 2 ----
    transpose_split_kernel<<<tG, tB>>>(W2, 0);
    transpose_split_kernel<<<tG, tB>>>(U2, 1);
    gemm_mma_kernel<<<gG, 256>>>(b2, 1);
    gru_recurrent_kernel<<<GRID_R, THR_R, SMEM_DYN>>>(b2 + G3, nullptr,
                                                      out, 0, state);
}